// round 14
// baseline (speedup 1.0000x reference)
#include <cuda_runtime.h>
#include <cuda_bf16.h>
#include <cstdint>

#define N_ROWS   32768
#define HDIM     1024
#define N_MOTIF  128
#define N_CLASS  16
#define K2       32
#define EPS_C    1e-4f
#define TAU_C    0.99f

#define NTILES   256
#define SPT      32
#define SPC      (NTILES * SPT)

// ---------------- device scratch ----------------
__device__ float g_cval[(size_t)N_CLASS * 8 * SPC];
__device__ int   g_cidx[(size_t)N_CLASS * SPC];
__device__ int   g_bcnt[N_CLASS * NTILES];
__device__ float g_loss_partial[128];
__device__ int   g_sel[N_MOTIF][K2];

#define NEG_INF __int_as_float(0xff800000)

__device__ __forceinline__ uint32_t smem_u32(const void* p) {
    uint32_t a;
    asm("{ .reg .u64 t; cvta.to.shared.u64 t, %1; cvt.u32.u64 %0, t; }" : "=r"(a) : "l"(p));
    return a;
}
__device__ __forceinline__ float rcp_newton(float x) {
    float y = __uint_as_float(0x7EF311C3u - __float_as_uint(x));
    y = y * fmaf(-x, y, 2.f);
    y = y * fmaf(-x, y, 2.f);
    y = y * fmaf(-x, y, 2.f);
    return y;
}
__device__ __forceinline__ uint32_t f2bf2(float lo, float hi) {
    __nv_bfloat162 h = __floats2bfloat162_rn(lo, hi);
    return *(uint32_t*)&h;
}
#define LDSM_X4(r0, r1, r2, r3, addr) \
    asm volatile("ldmatrix.sync.aligned.m8n8.x4.shared.b16 {%0,%1,%2,%3}, [%4];" \
        : "=r"(r0), "=r"(r1), "=r"(r2), "=r"(r3) : "r"(addr))

// ---------------- smem layout for k_gemm (R9-validated: KC=32) ----------------
#define KC      32
#define KP      40
#define XPS     129
#define SM_AB   0
#define SM_P    66048
#define SM_YC   (SM_P)
#define SM_ZN   (SM_P + 512)
#define SM_MN   (SM_P + 1024)
#define SM_PM   (SM_P + 1536)
#define SM_NS   (SM_P + 3584)
#define SM_LOSS (SM_P + 5632)
#define SM_SCNT (SM_P + 6144)
#define SM_MISC (SM_P + 6208)
#define SMEMB   (SM_P + 6272)

// ---------------- fused GEMM + distance + loss + candidate emit (R9 verbatim — at HMMA floor) ----------------
__global__ __launch_bounds__(512, 1)
void k_gemm(const float* __restrict__ z, const float* __restrict__ Mv,
            const int* __restrict__ yraw) {
    extern __shared__ char dsm[];
    __nv_bfloat16 (*sAB)[256][KP] = (__nv_bfloat16(*)[256][KP])(dsm + SM_AB);
    float (*xp)[XPS]   = (float(*)[XPS])(dsm);
    int*   yc_s  = (int*)  (dsm + SM_YC);
    float* zn_s  = (float*)(dsm + SM_ZN);
    float* mn_s  = (float*)(dsm + SM_MN);
    float* pm_s  = (float*)(dsm + SM_PM);
    float* ns_s  = (float*)(dsm + SM_NS);
    float* loss_s= (float*)(dsm + SM_LOSS);
    int*   scnt  = (int*)  (dsm + SM_SCNT);
    float* blk_loss = (float*)(dsm + SM_MISC);
    int*   is64p    = (int*)  (dsm + SM_MISC + 4);

    const int t    = threadIdx.x;
    const int lane = t & 31;
    const int w    = t >> 5;
    const int wm   = w >> 2;
    const int wn   = w & 3;

    const int srow = t >> 1;
    const int half = t & 1;
    const bool isZ = (srow < 128);

    if (t == 0) {
        *blk_loss = 0.f;
        int f = 1;
        for (int i = 0; i < 32; i++)
            if (yraw[2 * i + 1] != 0) { f = 0; break; }
        *is64p = f;
    }

    uint32_t aAddr[2][2], bAddr[2][2];
    {
        int arow = wm * 32 + (lane & 15);
        int acol = (lane < 16) ? 0 : 8;
        int g    = lane >> 3;
        int bk   = (g & 1) * 8;
        int bnb  = (g >= 2) ? 8 : 0;
#pragma unroll
        for (int buf = 0; buf < 2; buf++) {
            aAddr[buf][0] = smem_u32(&sAB[buf][arow][acol]);
            aAddr[buf][1] = smem_u32(&sAB[buf][arow + 16][acol]);
#pragma unroll
            for (int pair = 0; pair < 2; pair++) {
                int n = wn * 32 + pair * 16 + bnb + (lane & 7);
                bAddr[buf][pair] = smem_u32(&sAB[buf][128 + n][bk]);
            }
        }
    }
    __syncthreads();
    const int is64 = *is64p;

    for (int tile = 0; tile < 2; tile++) {
        const int tileIdx = blockIdx.x + tile * 128;
        const int r0 = tileIdx * 128;

        __syncthreads();
        if (t < 16)  scnt[t] = 0;
        if (t < 128) yc_s[t] = is64 ? yraw[2 * (r0 + t)] : yraw[r0 + t];

        const float* src = isZ ? (z  + (size_t)(r0 + srow) * HDIM + half * 16)
                               : (Mv + (size_t)(srow - 128) * HDIM + half * 16);

        float acc[2][4][4];
#pragma unroll
        for (int a = 0; a < 2; a++)
#pragma unroll
            for (int b = 0; b < 4; b++)
#pragma unroll
                for (int c = 0; c < 4; c++) acc[a][b][c] = 0.f;
        float sq = 0.f;

        float4 v[4];
#pragma unroll
        for (int j = 0; j < 4; j++) v[j] = *(const float4*)(src + 4 * j);
        {
#pragma unroll
            for (int j = 0; j < 4; j++) {
                sq = fmaf(v[j].x, v[j].x, sq); sq = fmaf(v[j].y, v[j].y, sq);
                sq = fmaf(v[j].z, v[j].z, sq); sq = fmaf(v[j].w, v[j].w, sq);
            }
            uint4 u0, u1;
            u0.x = f2bf2(v[0].x, v[0].y); u0.y = f2bf2(v[0].z, v[0].w);
            u0.z = f2bf2(v[1].x, v[1].y); u0.w = f2bf2(v[1].z, v[1].w);
            u1.x = f2bf2(v[2].x, v[2].y); u1.y = f2bf2(v[2].z, v[2].w);
            u1.z = f2bf2(v[3].x, v[3].y); u1.w = f2bf2(v[3].z, v[3].w);
            *(uint4*)&sAB[0][srow][half * 16]     = u0;
            *(uint4*)&sAB[0][srow][half * 16 + 8] = u1;
        }

        for (int ch = 0; ch < 32; ch++) {
            const int buf = ch & 1;
            __syncthreads();

            if (ch < 31) {
                const float* s2 = src + (ch + 1) * KC;
#pragma unroll
                for (int j = 0; j < 4; j++) v[j] = *(const float4*)(s2 + 4 * j);
            }

#pragma unroll
            for (int ks = 0; ks < 2; ks++) {
                uint32_t af[2][4];
                LDSM_X4(af[0][0], af[0][1], af[0][2], af[0][3], aAddr[buf][0] + ks * 32);
                LDSM_X4(af[1][0], af[1][1], af[1][2], af[1][3], aAddr[buf][1] + ks * 32);
                uint32_t bf[4][2];
                LDSM_X4(bf[0][0], bf[0][1], bf[1][0], bf[1][1], bAddr[buf][0] + ks * 32);
                LDSM_X4(bf[2][0], bf[2][1], bf[3][0], bf[3][1], bAddr[buf][1] + ks * 32);
#pragma unroll
                for (int mt = 0; mt < 2; mt++)
#pragma unroll
                    for (int nt = 0; nt < 4; nt++) {
                        asm volatile(
                            "mma.sync.aligned.m16n8k16.row.col.f32.bf16.bf16.f32 "
                            "{%0,%1,%2,%3},{%4,%5,%6,%7},{%8,%9},{%0,%1,%2,%3};"
                            : "+f"(acc[mt][nt][0]), "+f"(acc[mt][nt][1]),
                              "+f"(acc[mt][nt][2]), "+f"(acc[mt][nt][3])
                            : "r"(af[mt][0]), "r"(af[mt][1]), "r"(af[mt][2]), "r"(af[mt][3]),
                              "r"(bf[nt][0]), "r"(bf[nt][1]));
                    }
            }

            if (ch < 31) {
#pragma unroll
                for (int j = 0; j < 4; j++) {
                    sq = fmaf(v[j].x, v[j].x, sq); sq = fmaf(v[j].y, v[j].y, sq);
                    sq = fmaf(v[j].z, v[j].z, sq); sq = fmaf(v[j].w, v[j].w, sq);
                }
                uint4 u0, u1;
                u0.x = f2bf2(v[0].x, v[0].y); u0.y = f2bf2(v[0].z, v[0].w);
                u0.z = f2bf2(v[1].x, v[1].y); u0.w = f2bf2(v[1].z, v[1].w);
                u1.x = f2bf2(v[2].x, v[2].y); u1.y = f2bf2(v[2].z, v[2].w);
                u1.z = f2bf2(v[3].x, v[3].y); u1.w = f2bf2(v[3].z, v[3].w);
                const int nb = buf ^ 1;
                *(uint4*)&sAB[nb][srow][half * 16]     = u0;
                *(uint4*)&sAB[nb][srow][half * 16 + 8] = u1;
            }
        }

        {
            float o = __shfl_xor_sync(0xffffffffu, sq, 1);
            float tot = sq + o;
            if (half == 0) {
                if (isZ) zn_s[srow] = tot;
                else     mn_s[srow - 128] = tot;
            }
        }
        __syncthreads();

        {
            const int rA = lane >> 2;
#pragma unroll
            for (int mt = 0; mt < 2; mt++)
#pragma unroll
                for (int nt = 0; nt < 4; nt++)
#pragma unroll
                    for (int r = 0; r < 4; r++) {
                        int row = wm * 32 + mt * 16 + rA + 8 * (r >> 1);
                        int col = wn * 32 + nt * 8 + 2 * (lane & 3) + (r & 1);
                        xp[row][col] = acc[mt][nt][r];
                    }
        }
        __syncthreads();

        {
            const int row = t & 127;
            const int q   = t >> 7;
            const int c   = yc_s[row];
            const float znv = zn_s[row];
            float pmax = NEG_INF, nsum = 0.f;
#pragma unroll 8
            for (int i = 0; i < 32; i++) {
                int col = q * 32 + i;
                float d  = fmaf(-2.f, xp[row][col], znv + mn_s[col]);
                float x  = d + EPS_C;
                float dl = (1.f - EPS_C) * rcp_newton(x);
                float rr = 1.f + dl;
                float r2 = rr * rr;
                float s  = r2 * r2 * rr;
                if ((col >> 3) == c) pmax = fmaxf(pmax, s);
                else nsum += s;
            }
            pm_s[q * 128 + row] = pmax;
            ns_s[q * 128 + row] = nsum;

            if (q == 0) {
                int rank = atomicAdd(&scnt[c], 1);
                if (rank < SPT) {
                    int slot = tileIdx * SPT + rank;
                    g_cidx[c * SPC + slot] = r0 + row;
#pragma unroll
                    for (int m = 0; m < 8; m++) {
                        int col = 8 * c + m;
                        float d = fmaf(-2.f, xp[row][col], znv + mn_s[col]);
                        g_cval[(size_t)((c << 3) + m) * SPC + slot] = d;
                    }
                }
            }
        }
        __syncthreads();

        if (t < 128) {
            float P = fmaxf(fmaxf(pm_s[t], pm_s[128 + t]),
                            fmaxf(pm_s[256 + t], pm_s[384 + t]));
            float S = (ns_s[t] + ns_s[128 + t]) + (ns_s[256 + t] + ns_s[384 + t]);
            loss_s[t] = log1pf(S / P);
        }
        if (t < 16) g_bcnt[t * NTILES + tileIdx] = min(scnt[t], SPT);
        __syncthreads();
        for (int s = 64; s > 0; s >>= 1) {
            if (t < s) loss_s[t] += loss_s[t + s];
            __syncthreads();
        }
        if (t == 0) *blk_loss += loss_s[0];
    }

    if (t == 0) g_loss_partial[blockIdx.x] = *blk_loss;
}

// ---------------- selection: warp-local top-32 + single-warp merge (no z traffic) ----------------
#define CAPC 2560
#define TKT  512
#define NCV  5      // 5 x 512 = 2560 covers full CAPC

__device__ __forceinline__ bool better(float av, int ai, float bv, int bi) {
    return (av > bv) || (av == bv && ai < bi);
}

__global__ __launch_bounds__(TKT)
void k_sel(float* __restrict__ out, int writeLoss) {
    __shared__ float sv[CAPC];
    __shared__ int   si[CAPC];
    __shared__ int   pre[256];
    __shared__ int   wsum[8], wscan[8];
    __shared__ float wtv[16][K2];
    __shared__ int   wti[16][K2];
    __shared__ float lred[128];
    __shared__ int   ntot;

    const int t    = threadIdx.x;
    const int lane = t & 31;
    const int w    = t >> 5;
    const int j    = blockIdx.x;
    const int c    = j >> 3;
    const int m    = j & 7;

    // segment counts + prefix sum over 256 tiles (threads 0..255)
    int cnt = 0;
    if (t < 256) {
        cnt = g_bcnt[c * NTILES + t];
        int v = cnt;
#pragma unroll
        for (int o = 1; o < 32; o <<= 1) {
            int nvv = __shfl_up_sync(0xffffffffu, v, o);
            if (lane >= o) v += nvv;
        }
        if (lane == 31) wsum[w] = v;
        pre[t] = v - cnt;
    }
    __syncthreads();
    if (t < 8) {
        int s = wsum[t];
#pragma unroll
        for (int o = 1; o < 8; o <<= 1) {
            int nvv = __shfl_up_sync(0xffu, s, o);
            if ((t & 7) >= o) s += nvv;
        }
        wscan[t] = s;
    }
    __syncthreads();
    if (t < 256) {
        int excl = pre[t] + (w > 0 ? wscan[w - 1] : 0);
        pre[t] = excl;
        if (t == 255) ntot = min(excl + cnt, CAPC);
    }
    __syncthreads();

    // gather candidates into compact smem arrays
    if (t < 256) {
        const float* cvp = g_cval + (size_t)((c << 3) + m) * SPC + t * SPT;
        const int*   cip = g_cidx + (size_t)c * SPC + t * SPT;
        int off = pre[t];
        for (int i = 0; i < cnt; i++) {
            if (off + i < CAPC) { sv[off + i] = cvp[i]; si[off + i] = cip[i]; }
        }
    }
    __syncthreads();
    const int n = ntot;

    // phase B: each warp extracts its own sorted top-32 (no block barriers)
    {
        float cv[NCV]; int ci[NCV];
#pragma unroll
        for (int u = 0; u < NCV; u++) {
            int p = t + u * TKT;
            if (p < n) { cv[u] = sv[p]; ci[u] = si[p]; }
            else       { cv[u] = NEG_INF; ci[u] = 0x7fffffff; }
        }
#pragma unroll 4
        for (int k = 0; k < K2; k++) {
            float bv = cv[0]; int bi = ci[0]; int bu = 0;
#pragma unroll
            for (int u = 1; u < NCV; u++)
                if (better(cv[u], ci[u], bv, bi)) { bv = cv[u]; bi = ci[u]; bu = u; }
            float rv = bv; int ri = bi; int rl = lane;
#pragma unroll
            for (int o = 16; o > 0; o >>= 1) {
                float ov = __shfl_xor_sync(0xffffffffu, rv, o);
                int   oi = __shfl_xor_sync(0xffffffffu, ri, o);
                int   ol = __shfl_xor_sync(0xffffffffu, rl, o);
                if (better(ov, oi, rv, ri)) { rv = ov; ri = oi; rl = ol; }
            }
            if (lane == 0) { wtv[w][k] = rv; wti[w][k] = ri; }
            // predicated clear: static indexing keeps cv/ci in registers
            {
                const bool win = (lane == rl);
#pragma unroll
                for (int u = 0; u < NCV; u++) {
                    bool kill = win && (u == bu);
                    cv[u] = kill ? NEG_INF : cv[u];
                    ci[u] = kill ? 0x7fffffff : ci[u];
                }
            }
        }
    }
    __syncthreads();

    // phase C: warp 0 merges 16 sorted lists, writes g_sel
    if (w == 0) {
        int head = 0;
        float hv = (lane < 16) ? wtv[lane][0] : NEG_INF;
        int   hi = (lane < 16) ? wti[lane][0] : 0x7fffffff;
        for (int k = 0; k < K2; k++) {
            float rv = hv; int ri = hi; int rl = lane;
#pragma unroll
            for (int o = 16; o > 0; o >>= 1) {
                float ov = __shfl_xor_sync(0xffffffffu, rv, o);
                int   oi = __shfl_xor_sync(0xffffffffu, ri, o);
                int   ol = __shfl_xor_sync(0xffffffffu, rl, o);
                if (better(ov, oi, rv, ri)) { rv = ov; ri = oi; rl = ol; }
            }
            if (lane == 0) g_sel[j][k] = (rv == NEG_INF) ? 0 : ri;
            if (lane == rl) {
                head++;
                hv = (head < K2) ? wtv[lane][head] : NEG_INF;
                hi = (head < K2) ? wti[lane][head] : 0x7fffffff;
            }
        }
    }

    // block 0: loss finalize
    if (j == 0 && writeLoss) {
        __syncthreads();
        if (t < 128) lred[t] = g_loss_partial[t];
        __syncthreads();
        for (int s = 64; s > 0; s >>= 1) {
            if (t < s) lred[t] += lred[t + s];
            __syncthreads();
        }
        if (t == 0) out[0] = lred[0] * (1.f / (float)N_ROWS);
    }
}

// ---------------- update: bandwidth-bound gather-mean + EMA blend (512 blocks) ----------------
__global__ __launch_bounds__(256)
void k_upd(const float* __restrict__ z, const float* __restrict__ M,
           float* __restrict__ out, int moff) {
    __shared__ int sel_s[K2];
    const int t = threadIdx.x;
    const int j = blockIdx.x >> 2;
    const int s = blockIdx.x & 3;
    const int col = s * 256 + t;

    if (t < K2) sel_s[t] = g_sel[j][t];
    __syncthreads();

    float a = 0.f;
#pragma unroll 8
    for (int k = 0; k < K2; k++)
        a += z[(size_t)sel_s[k] * HDIM + col];

    out[moff + (size_t)j * HDIM + col] =
        TAU_C * M[(size_t)j * HDIM + col] + (1.f - TAU_C) * (a * (1.f / (float)K2));
}

// ---------------- entry ----------------
extern "C" void kernel_launch(void* const* d_in, const int* in_sizes, int n_in,
                              void* d_out, int out_size) {
    const float* z = (const float*)d_in[0];
    const float* M = (const float*)d_in[1];
    const int*   y = (const int*)d_in[2];
    float* out = (float*)d_out;

    int moff, writeM, writeLoss;
    if (out_size >= N_MOTIF * HDIM + 1)  { moff = 1; writeM = 1; writeLoss = 1; }
    else if (out_size >= N_MOTIF * HDIM) { moff = 0; writeM = 1; writeLoss = 0; }
    else                                 { moff = 0; writeM = 0; writeLoss = 1; }

    cudaFuncSetAttribute(k_gemm, cudaFuncAttributeMaxDynamicSharedMemorySize, SMEMB);

    k_gemm<<<128, 512, SMEMB>>>(z, M, y);
    k_sel<<<N_MOTIF, TKT>>>(out, writeLoss);
    if (writeM) k_upd<<<N_MOTIF * 4, 256>>>(z, M, out, moff);
}

// round 15
// speedup vs baseline: 1.5792x; 1.5792x over previous
#include <cuda_runtime.h>
#include <cuda_bf16.h>
#include <cstdint>

#define N_ROWS   32768
#define HDIM     1024
#define N_MOTIF  128
#define N_CLASS  16
#define K2       32
#define EPS_C    1e-4f
#define TAU_C    0.99f

#define NTILES   256
#define SPT      32
#define SPC      (NTILES * SPT)

// ---------------- device scratch ----------------
__device__ float g_cval[(size_t)N_CLASS * 8 * SPC];
__device__ int   g_cidx[(size_t)N_CLASS * SPC];
__device__ int   g_bcnt[N_CLASS * NTILES];
__device__ float g_loss_partial[128];
__device__ int   g_sel[N_MOTIF][K2];

#define NEG_INF __int_as_float(0xff800000)

__device__ __forceinline__ uint32_t smem_u32(const void* p) {
    uint32_t a;
    asm("{ .reg .u64 t; cvta.to.shared.u64 t, %1; cvt.u32.u64 %0, t; }" : "=r"(a) : "l"(p));
    return a;
}
__device__ __forceinline__ float rcp_newton(float x) {
    float y = __uint_as_float(0x7EF311C3u - __float_as_uint(x));
    y = y * fmaf(-x, y, 2.f);
    y = y * fmaf(-x, y, 2.f);
    y = y * fmaf(-x, y, 2.f);
    return y;
}
__device__ __forceinline__ uint32_t f2bf2(float lo, float hi) {
    __nv_bfloat162 h = __floats2bfloat162_rn(lo, hi);
    return *(uint32_t*)&h;
}
#define LDSM_X4(r0, r1, r2, r3, addr) \
    asm volatile("ldmatrix.sync.aligned.m8n8.x4.shared.b16 {%0,%1,%2,%3}, [%4];" \
        : "=r"(r0), "=r"(r1), "=r"(r2), "=r"(r3) : "r"(addr))

// ---------------- smem layout: KC=16, KP=24, 4 buffers ----------------
#define KC      16
#define KP      24          // 48B row stride: ldmatrix-conflict-free (validated R5)
#define BUFB    (256 * KP * 2)   // 12288 B per buffer
#define XPS     129
#define SM_AB   0           // 4 bufs x 12288 = 49152 B (union with XP 66048)
#define SM_P    66048       // xp: 128 x 129 f32
#define SM_YC   (SM_P)
#define SM_ZN   (SM_P + 512)
#define SM_MN   (SM_P + 1024)
#define SM_PM   (SM_P + 1536)
#define SM_NS   (SM_P + 3584)
#define SM_LOSS (SM_P + 5632)
#define SM_SCNT (SM_P + 6144)
#define SM_MISC (SM_P + 6208)
#define SMEMB   (SM_P + 6272)

// convert 8 floats (2 float4) -> 8 bf16, accumulate sumsq, one STS.128
#define CVT_STORE(VS, CB)                                                       \
    do {                                                                        \
        float4 p0 = v[VS][0], p1 = v[VS][1];                                    \
        sq = fmaf(p0.x, p0.x, sq); sq = fmaf(p0.y, p0.y, sq);                   \
        sq = fmaf(p0.z, p0.z, sq); sq = fmaf(p0.w, p0.w, sq);                   \
        sq = fmaf(p1.x, p1.x, sq); sq = fmaf(p1.y, p1.y, sq);                   \
        sq = fmaf(p1.z, p1.z, sq); sq = fmaf(p1.w, p1.w, sq);                   \
        uint4 u;                                                                \
        u.x = f2bf2(p0.x, p0.y); u.y = f2bf2(p0.z, p0.w);                       \
        u.z = f2bf2(p1.x, p1.y); u.w = f2bf2(p1.z, p1.w);                       \
        *(uint4*)(abp + (CB) * BUFB + stoff) = u;                               \
    } while (0)

// one pipeline step: issue LDG(ch+3)->v[IS], MMA buf[MB], convert v[CS]->buf[CB], barrier
#define STEP(CH, IS, CS, MB, CB)                                                \
    do {                                                                        \
        const int ch_ = (CH);                                                   \
        if (ch_ < 61) {                                                         \
            const float* s2 = src + (ch_ + 3) * KC;                             \
            v[IS][0] = *(const float4*)(s2);                                    \
            v[IS][1] = *(const float4*)(s2 + 4);                                \
        }                                                                       \
        uint32_t af[2][4];                                                      \
        LDSM_X4(af[0][0], af[0][1], af[0][2], af[0][3], aA0 + (MB) * BUFB);     \
        LDSM_X4(af[1][0], af[1][1], af[1][2], af[1][3], aA1 + (MB) * BUFB);     \
        uint32_t bfr[4][2];                                                     \
        LDSM_X4(bfr[0][0], bfr[0][1], bfr[1][0], bfr[1][1], bB0 + (MB) * BUFB); \
        LDSM_X4(bfr[2][0], bfr[2][1], bfr[3][0], bfr[3][1], bB1 + (MB) * BUFB); \
        _Pragma("unroll")                                                       \
        for (int mt = 0; mt < 2; mt++)                                          \
            _Pragma("unroll")                                                   \
            for (int nt = 0; nt < 4; nt++) {                                    \
                asm volatile(                                                   \
                    "mma.sync.aligned.m16n8k16.row.col.f32.bf16.bf16.f32 "      \
                    "{%0,%1,%2,%3},{%4,%5,%6,%7},{%8,%9},{%0,%1,%2,%3};"        \
                    : "+f"(acc[mt][nt][0]), "+f"(acc[mt][nt][1]),               \
                      "+f"(acc[mt][nt][2]), "+f"(acc[mt][nt][3])                \
                    : "r"(af[mt][0]), "r"(af[mt][1]),                           \
                      "r"(af[mt][2]), "r"(af[mt][3]),                           \
                      "r"(bfr[nt][0]), "r"(bfr[nt][1]));                        \
            }                                                                   \
        if (ch_ < 63) { CVT_STORE(CS, CB); }                                    \
        __syncthreads();                                                        \
    } while (0)

// ---------------- fused GEMM + distance + loss + candidate emit ----------------
// 512 threads (16 warps 4x4), tile 128x128, KC=16, distance-3 pipeline, 4 bufs.
__global__ __launch_bounds__(512, 1)
void k_gemm(const float* __restrict__ z, const float* __restrict__ Mv,
            const int* __restrict__ yraw) {
    extern __shared__ char dsm[];
    float (*xp)[XPS]   = (float(*)[XPS])(dsm);
    int*   yc_s  = (int*)  (dsm + SM_YC);
    float* zn_s  = (float*)(dsm + SM_ZN);
    float* mn_s  = (float*)(dsm + SM_MN);
    float* pm_s  = (float*)(dsm + SM_PM);
    float* ns_s  = (float*)(dsm + SM_NS);
    float* loss_s= (float*)(dsm + SM_LOSS);
    int*   scnt  = (int*)  (dsm + SM_SCNT);
    float* blk_loss = (float*)(dsm + SM_MISC);
    int*   is64p    = (int*)  (dsm + SM_MISC + 4);
    char*  abp   = dsm + SM_AB;

    const int t    = threadIdx.x;
    const int lane = t & 31;
    const int w    = t >> 5;
    const int wm   = w >> 2;
    const int wn   = w & 3;

    const int srow = t >> 1;       // 0..255 (0-127 z, 128-255 M)
    const int half = t & 1;
    const bool isZ = (srow < 128);
    const uint32_t stoff = (uint32_t)(srow * (KP * 2) + half * 16);

    if (t == 0) {
        *blk_loss = 0.f;
        int f = 1;
        for (int i = 0; i < 32; i++)
            if (yraw[2 * i + 1] != 0) { f = 0; break; }
        *is64p = f;
    }

    // ldmatrix base addresses for buffer 0 (R5-validated fragment layout)
    uint32_t aA0, aA1, bB0, bB1;
    {
        __nv_bfloat16 (*sAB)[KP] = (__nv_bfloat16(*)[KP])abp;
        int arow = wm * 32 + (lane & 15);
        int acol = (lane < 16) ? 0 : 8;
        int g    = lane >> 3;
        int bk   = (g & 1) * 8;
        int bnb  = (g >= 2) ? 8 : 0;
        aA0 = smem_u32(&sAB[arow][acol]);
        aA1 = smem_u32(&sAB[arow + 16][acol]);
        int n0 = wn * 32 + 0 * 16 + bnb + (lane & 7);
        int n1 = wn * 32 + 1 * 16 + bnb + (lane & 7);
        bB0 = smem_u32(&sAB[128 + n0][bk]);
        bB1 = smem_u32(&sAB[128 + n1][bk]);
    }
    __syncthreads();
    const int is64 = *is64p;

    for (int tile = 0; tile < 2; tile++) {
        const int tileIdx = blockIdx.x + tile * 128;
        const int r0 = tileIdx * 128;

        __syncthreads();   // previous epilogue done before AB reuse
        if (t < 16)  scnt[t] = 0;
        if (t < 128) yc_s[t] = is64 ? yraw[2 * (r0 + t)] : yraw[r0 + t];

        const float* src = isZ ? (z  + (size_t)(r0 + srow) * HDIM + half * 8)
                               : (Mv + (size_t)(srow - 128) * HDIM + half * 8);

        float acc[2][4][4];
#pragma unroll
        for (int a = 0; a < 2; a++)
#pragma unroll
            for (int b = 0; b < 4; b++)
#pragma unroll
                for (int c = 0; c < 4; c++) acc[a][b][c] = 0.f;
        float sq = 0.f;

        // prologue: load chunks 0,1,2; convert chunk 0 -> buf 0
        float4 v[4][2];
#pragma unroll
        for (int p = 0; p < 3; p++) {
            const float* sp = src + p * KC;
            v[p][0] = *(const float4*)(sp);
            v[p][1] = *(const float4*)(sp + 4);
        }
        CVT_STORE(0, 0);
        __syncthreads();

        // mainloop: 64 chunks, statically unrolled x4 (all set indices literal)
        for (int cg = 0; cg < 16; cg++) {
            const int chb = cg * 4;
            STEP(chb + 0, 3, 1, 0, 1);
            STEP(chb + 1, 0, 2, 1, 2);
            STEP(chb + 2, 1, 3, 2, 3);
            STEP(chb + 3, 2, 0, 3, 0);
        }

        // row norms: combine half-row partials (adjacent lanes)
        {
            float o = __shfl_xor_sync(0xffffffffu, sq, 1);
            float tot = sq + o;
            if (half == 0) {
                if (isZ) zn_s[srow] = tot;
                else     mn_s[srow - 128] = tot;
            }
        }
        __syncthreads();   // all MMA/LDSM done -> safe to overwrite AB as xp

        // stage acc -> xp[128][129]
        {
            const int rA = lane >> 2;
#pragma unroll
            for (int mt = 0; mt < 2; mt++)
#pragma unroll
                for (int nt = 0; nt < 4; nt++)
#pragma unroll
                    for (int r = 0; r < 4; r++) {
                        int row = wm * 32 + mt * 16 + rA + 8 * (r >> 1);
                        int col = wn * 32 + nt * 8 + 2 * (lane & 3) + (r & 1);
                        xp[row][col] = acc[mt][nt][r];
                    }
        }
        __syncthreads();

        // stats + candidate emit
        {
            const int row = t & 127;
            const int q   = t >> 7;
            const int c   = yc_s[row];
            const float znv = zn_s[row];
            float pmax = NEG_INF, nsum = 0.f;
#pragma unroll 8
            for (int i = 0; i < 32; i++) {
                int col = q * 32 + i;
                float d  = fmaf(-2.f, xp[row][col], znv + mn_s[col]);
                float x  = d + EPS_C;
                float dl = (1.f - EPS_C) * rcp_newton(x);
                float rr = 1.f + dl;
                float r2 = rr * rr;
                float s  = r2 * r2 * rr;
                if ((col >> 3) == c) pmax = fmaxf(pmax, s);
                else nsum += s;
            }
            pm_s[q * 128 + row] = pmax;
            ns_s[q * 128 + row] = nsum;

            if (q == 0) {
                int rank = atomicAdd(&scnt[c], 1);
                if (rank < SPT) {
                    int slot = tileIdx * SPT + rank;
                    g_cidx[c * SPC + slot] = r0 + row;
#pragma unroll
                    for (int m = 0; m < 8; m++) {
                        int col = 8 * c + m;
                        float d = fmaf(-2.f, xp[row][col], znv + mn_s[col]);
                        g_cval[(size_t)((c << 3) + m) * SPC + slot] = d;
                    }
                }
            }
        }
        __syncthreads();

        if (t < 128) {
            float P = fmaxf(fmaxf(pm_s[t], pm_s[128 + t]),
                            fmaxf(pm_s[256 + t], pm_s[384 + t]));
            float S = (ns_s[t] + ns_s[128 + t]) + (ns_s[256 + t] + ns_s[384 + t]);
            loss_s[t] = log1pf(S / P);
        }
        if (t < 16) g_bcnt[t * NTILES + tileIdx] = min(scnt[t], SPT);
        __syncthreads();
        for (int s = 64; s > 0; s >>= 1) {
            if (t < s) loss_s[t] += loss_s[t + s];
            __syncthreads();
        }
        if (t == 0) *blk_loss += loss_s[0];
    }

    if (t == 0) g_loss_partial[blockIdx.x] = *blk_loss;
}

// ---------------- selection: warp-local top-32 + single-warp merge ----------------
#define CAPC 2560
#define TKT  512
#define NCV  5

__device__ __forceinline__ bool better(float av, int ai, float bv, int bi) {
    return (av > bv) || (av == bv && ai < bi);
}

__global__ __launch_bounds__(TKT)
void k_sel(float* __restrict__ out, int writeLoss) {
    __shared__ float sv[CAPC];
    __shared__ int   si[CAPC];
    __shared__ int   pre[256];
    __shared__ int   wsum[8], wscan[8];
    __shared__ float wtv[16][K2];
    __shared__ int   wti[16][K2];
    __shared__ float lred[128];
    __shared__ int   ntot;

    const int t    = threadIdx.x;
    const int lane = t & 31;
    const int w    = t >> 5;
    const int j    = blockIdx.x;
    const int c    = j >> 3;
    const int m    = j & 7;

    int cnt = 0;
    if (t < 256) {
        cnt = g_bcnt[c * NTILES + t];
        int v = cnt;
#pragma unroll
        for (int o = 1; o < 32; o <<= 1) {
            int nvv = __shfl_up_sync(0xffffffffu, v, o);
            if (lane >= o) v += nvv;
        }
        if (lane == 31) wsum[w] = v;
        pre[t] = v - cnt;
    }
    __syncthreads();
    if (t < 8) {
        int s = wsum[t];
#pragma unroll
        for (int o = 1; o < 8; o <<= 1) {
            int nvv = __shfl_up_sync(0xffu, s, o);
            if ((t & 7) >= o) s += nvv;
        }
        wscan[t] = s;
    }
    __syncthreads();
    if (t < 256) {
        int excl = pre[t] + (w > 0 ? wscan[w - 1] : 0);
        pre[t] = excl;
        if (t == 255) ntot = min(excl + cnt, CAPC);
    }
    __syncthreads();

    if (t < 256) {
        const float* cvp = g_cval + (size_t)((c << 3) + m) * SPC + t * SPT;
        const int*   cip = g_cidx + (size_t)c * SPC + t * SPT;
        int off = pre[t];
        for (int i = 0; i < cnt; i++) {
            if (off + i < CAPC) { sv[off + i] = cvp[i]; si[off + i] = cip[i]; }
        }
    }
    __syncthreads();
    const int n = ntot;

    {
        float cv[NCV]; int ci[NCV];
#pragma unroll
        for (int u = 0; u < NCV; u++) {
            int p = t + u * TKT;
            if (p < n) { cv[u] = sv[p]; ci[u] = si[p]; }
            else       { cv[u] = NEG_INF; ci[u] = 0x7fffffff; }
        }
#pragma unroll 4
        for (int k = 0; k < K2; k++) {
            float bv = cv[0]; int bi = ci[0]; int bu = 0;
#pragma unroll
            for (int u = 1; u < NCV; u++)
                if (better(cv[u], ci[u], bv, bi)) { bv = cv[u]; bi = ci[u]; bu = u; }
            float rv = bv; int ri = bi; int rl = lane;
#pragma unroll
            for (int o = 16; o > 0; o >>= 1) {
                float ov = __shfl_xor_sync(0xffffffffu, rv, o);
                int   oi = __shfl_xor_sync(0xffffffffu, ri, o);
                int   ol = __shfl_xor_sync(0xffffffffu, rl, o);
                if (better(ov, oi, rv, ri)) { rv = ov; ri = oi; rl = ol; }
            }
            if (lane == 0) { wtv[w][k] = rv; wti[w][k] = ri; }
            {
                const bool win = (lane == rl);
#pragma unroll
                for (int u = 0; u < NCV; u++) {
                    bool kill = win && (u == bu);
                    cv[u] = kill ? NEG_INF : cv[u];
                    ci[u] = kill ? 0x7fffffff : ci[u];
                }
            }
        }
    }
    __syncthreads();

    if (w == 0) {
        int head = 0;
        float hv = (lane < 16) ? wtv[lane][0] : NEG_INF;
        int   hi = (lane < 16) ? wti[lane][0] : 0x7fffffff;
        for (int k = 0; k < K2; k++) {
            float rv = hv; int ri = hi; int rl = lane;
#pragma unroll
            for (int o = 16; o > 0; o >>= 1) {
                float ov = __shfl_xor_sync(0xffffffffu, rv, o);
                int   oi = __shfl_xor_sync(0xffffffffu, ri, o);
                int   ol = __shfl_xor_sync(0xffffffffu, rl, o);
                if (better(ov, oi, rv, ri)) { rv = ov; ri = oi; rl = ol; }
            }
            if (lane == 0) g_sel[j][k] = (rv == NEG_INF) ? 0 : ri;
            if (lane == rl) {
                head++;
                hv = (head < K2) ? wtv[lane][head] : NEG_INF;
                hi = (head < K2) ? wti[lane][head] : 0x7fffffff;
            }
        }
    }

    if (j == 0 && writeLoss) {
        __syncthreads();
        if (t < 128) lred[t] = g_loss_partial[t];
        __syncthreads();
        for (int s = 64; s > 0; s >>= 1) {
            if (t < s) lred[t] += lred[t + s];
            __syncthreads();
        }
        if (t == 0) out[0] = lred[0] * (1.f / (float)N_ROWS);
    }
}

// ---------------- update: bandwidth-bound gather-mean + EMA blend ----------------
__global__ __launch_bounds__(256)
void k_upd(const float* __restrict__ z, const float* __restrict__ M,
           float* __restrict__ out, int moff) {
    __shared__ int sel_s[K2];
    const int t = threadIdx.x;
    const int j = blockIdx.x >> 2;
    const int s = blockIdx.x & 3;
    const int col = s * 256 + t;

    if (t < K2) sel_s[t] = g_sel[j][t];
    __syncthreads();

    float a = 0.f;
#pragma unroll 8
    for (int k = 0; k < K2; k++)
        a += z[(size_t)sel_s[k] * HDIM + col];

    out[moff + (size_t)j * HDIM + col] =
        TAU_C * M[(size_t)j * HDIM + col] + (1.f - TAU_C) * (a * (1.f / (float)K2));
}

// ---------------- entry ----------------
extern "C" void kernel_launch(void* const* d_in, const int* in_sizes, int n_in,
                              void* d_out, int out_size) {
    const float* z = (const float*)d_in[0];
    const float* M = (const float*)d_in[1];
    const int*   y = (const int*)d_in[2];
    float* out = (float*)d_out;

    int moff, writeM, writeLoss;
    if (out_size >= N_MOTIF * HDIM + 1)  { moff = 1; writeM = 1; writeLoss = 1; }
    else if (out_size >= N_MOTIF * HDIM) { moff = 0; writeM = 1; writeLoss = 0; }
    else                                 { moff = 0; writeM = 0; writeLoss = 1; }

    cudaFuncSetAttribute(k_gemm, cudaFuncAttributeMaxDynamicSharedMemorySize, SMEMB);

    k_gemm<<<128, 512, SMEMB>>>(z, M, y);
    k_sel<<<N_MOTIF, TKT>>>(out, writeLoss);
    if (writeM) k_upd<<<N_MOTIF * 4, 256>>>(z, M, out, moff);
}

// round 16
// speedup vs baseline: 1.6987x; 1.0757x over previous
#include <cuda_runtime.h>
#include <cuda_bf16.h>
#include <cstdint>

#define N_ROWS   32768
#define HDIM     1024
#define N_MOTIF  128
#define N_CLASS  16
#define K2       32
#define EPS_C    1e-4f
#define TAU_C    0.99f

#define NTILES   256
#define SPT      32
#define SPC      (NTILES * SPT)

// ---------------- device scratch ----------------
__device__ float g_cval[(size_t)N_CLASS * 8 * SPC];
__device__ int   g_cidx[(size_t)N_CLASS * SPC];
__device__ int   g_bcnt[N_CLASS * NTILES];
__device__ float g_loss_partial[NTILES];
__device__ int   g_sel[N_MOTIF][K2];

#define NEG_INF __int_as_float(0xff800000)

__device__ __forceinline__ uint32_t smem_u32(const void* p) {
    uint32_t a;
    asm("{ .reg .u64 t; cvta.to.shared.u64 t, %1; cvt.u32.u64 %0, t; }" : "=r"(a) : "l"(p));
    return a;
}
__device__ __forceinline__ float rcp_newton(float x) {
    float y = __uint_as_float(0x7EF311C3u - __float_as_uint(x));
    y = y * fmaf(-x, y, 2.f);
    y = y * fmaf(-x, y, 2.f);
    y = y * fmaf(-x, y, 2.f);
    return y;
}
__device__ __forceinline__ uint32_t f2bf2(float lo, float hi) {
    __nv_bfloat162 h = __floats2bfloat162_rn(lo, hi);
    return *(uint32_t*)&h;
}
#define LDSM_X4(r0, r1, r2, r3, addr) \
    asm volatile("ldmatrix.sync.aligned.m8n8.x4.shared.b16 {%0,%1,%2,%3}, [%4];" \
        : "=r"(r0), "=r"(r1), "=r"(r2), "=r"(r3) : "r"(addr))

#define MMA16816(ACC, AF, B0, B1)                                               \
    asm volatile(                                                               \
        "mma.sync.aligned.m16n8k16.row.col.f32.bf16.bf16.f32 "                  \
        "{%0,%1,%2,%3},{%4,%5,%6,%7},{%8,%9},{%0,%1,%2,%3};"                    \
        : "+f"((ACC)[0]), "+f"((ACC)[1]), "+f"((ACC)[2]), "+f"((ACC)[3])        \
        : "r"((AF)[0]), "r"((AF)[1]), "r"((AF)[2]), "r"((AF)[3]),               \
          "r"(B0), "r"(B1))

// ---------------- smem layout: KC=16, KP=24, 2 buffers, 256-thread CTA ----------------
#define KC      16
#define KP      24               // 48B row stride, ldmatrix-conflict-free (R5-validated)
#define BUFB    (256 * KP * 2)   // 12288 B per buffer
#define XPS     129
#define SM_AB   0                // 2 x 12288 = 24576 (union with XP 66048)
#define SM_P    66048            // xp: 128 x 129 f32
#define SM_YC   (SM_P)
#define SM_ZN   (SM_P + 512)
#define SM_MN   (SM_P + 1024)
#define SM_PM   (SM_P + 1536)    // [2][128]
#define SM_NS   (SM_P + 2560)    // [2][128]
#define SM_LOSS (SM_P + 3584)    // 128 f32
#define SM_SCNT (SM_P + 4096)    // 16 int
#define SM_MISC (SM_P + 4160)
#define SMEMB   (SM_P + 4224)

// ---------------- fused GEMM + distance + loss + candidate emit ----------------
// 256 threads (8 warps, 4x2), warp tile 32x64, block tile 128x128, 1 tile/block,
// grid 256, 2 CTAs/SM. KC=16 double-buffered, prefetch-1 (cross-CTA hides the rest).
__global__ __launch_bounds__(256, 2)
void k_gemm(const float* __restrict__ z, const float* __restrict__ Mv,
            const int* __restrict__ yraw) {
    extern __shared__ char dsm[];
    float (*xp)[XPS]   = (float(*)[XPS])(dsm);
    int*   yc_s  = (int*)  (dsm + SM_YC);
    float* zn_s  = (float*)(dsm + SM_ZN);
    float* mn_s  = (float*)(dsm + SM_MN);
    float* pm_s  = (float*)(dsm + SM_PM);
    float* ns_s  = (float*)(dsm + SM_NS);
    float* loss_s= (float*)(dsm + SM_LOSS);
    int*   scnt  = (int*)  (dsm + SM_SCNT);
    int*   is64p = (int*)  (dsm + SM_MISC);
    char*  abp   = dsm + SM_AB;

    const int t    = threadIdx.x;
    const int lane = t & 31;
    const int w    = t >> 5;
    const int wm   = w >> 1;    // 0..3 (32-row band)
    const int wn   = w & 1;     // 0..1 (64-col half)

    const int lrow = t >> 1;    // 0..127: this thread's z row AND M row
    const int half = t & 1;
    const uint32_t stZ = (uint32_t)(lrow * (KP * 2) + half * 16);
    const uint32_t stM = (uint32_t)((128 + lrow) * (KP * 2) + half * 16);

    const int tileIdx = blockIdx.x;
    const int r0 = tileIdx * 128;

    if (t == 0) {
        int f = 1;
        for (int i = 0; i < 32; i++)
            if (yraw[2 * i + 1] != 0) { f = 0; break; }
        *is64p = f;
    }
    if (t < 16) scnt[t] = 0;

    // ldmatrix base addresses (buffer 0); add (ch&1)*BUFB at use
    uint32_t aA0, aA1, bB[4];
    {
        __nv_bfloat16 (*sAB)[KP] = (__nv_bfloat16(*)[KP])abp;
        int arow = wm * 32 + (lane & 15);
        int acol = (lane < 16) ? 0 : 8;
        int g    = lane >> 3;
        int bk   = (g & 1) * 8;
        int bnb  = (g >= 2) ? 8 : 0;
        aA0 = smem_u32(&sAB[arow][acol]);
        aA1 = smem_u32(&sAB[arow + 16][acol]);
#pragma unroll
        for (int p = 0; p < 4; p++) {
            int n = wn * 64 + p * 16 + bnb + (lane & 7);
            bB[p] = smem_u32(&sAB[128 + n][bk]);
        }
    }
    __syncthreads();
    const int is64 = *is64p;
    if (t < 128) yc_s[t] = is64 ? yraw[2 * (r0 + t)] : yraw[r0 + t];

    const float* zsrc = z  + (size_t)(r0 + lrow) * HDIM + half * 8;
    const float* msrc = Mv + (size_t)lrow        * HDIM + half * 8;

    float acc[2][8][4];
#pragma unroll
    for (int a = 0; a < 2; a++)
#pragma unroll
        for (int b = 0; b < 8; b++)
#pragma unroll
            for (int c = 0; c < 4; c++) acc[a][b][c] = 0.f;
    float sqz = 0.f, sqm = 0.f;

    // prologue: chunk 0 -> buf 0
    float4 v[4];
    v[0] = *(const float4*)(zsrc);     v[1] = *(const float4*)(zsrc + 4);
    v[2] = *(const float4*)(msrc);     v[3] = *(const float4*)(msrc + 4);
    {
        sqz = fmaf(v[0].x, v[0].x, sqz); sqz = fmaf(v[0].y, v[0].y, sqz);
        sqz = fmaf(v[0].z, v[0].z, sqz); sqz = fmaf(v[0].w, v[0].w, sqz);
        sqz = fmaf(v[1].x, v[1].x, sqz); sqz = fmaf(v[1].y, v[1].y, sqz);
        sqz = fmaf(v[1].z, v[1].z, sqz); sqz = fmaf(v[1].w, v[1].w, sqz);
        uint4 u;
        u.x = f2bf2(v[0].x, v[0].y); u.y = f2bf2(v[0].z, v[0].w);
        u.z = f2bf2(v[1].x, v[1].y); u.w = f2bf2(v[1].z, v[1].w);
        *(uint4*)(abp + stZ) = u;
        sqm = fmaf(v[2].x, v[2].x, sqm); sqm = fmaf(v[2].y, v[2].y, sqm);
        sqm = fmaf(v[2].z, v[2].z, sqm); sqm = fmaf(v[2].w, v[2].w, sqm);
        sqm = fmaf(v[3].x, v[3].x, sqm); sqm = fmaf(v[3].y, v[3].y, sqm);
        sqm = fmaf(v[3].z, v[3].z, sqm); sqm = fmaf(v[3].w, v[3].w, sqm);
        uint4 u2;
        u2.x = f2bf2(v[2].x, v[2].y); u2.y = f2bf2(v[2].z, v[2].w);
        u2.z = f2bf2(v[3].x, v[3].y); u2.w = f2bf2(v[3].z, v[3].w);
        *(uint4*)(abp + stM) = u2;
    }

    for (int ch = 0; ch < 64; ch++) {
        const uint32_t boff = (uint32_t)(ch & 1) * BUFB;
        __syncthreads();

        if (ch < 63) {
            const float* zs2 = zsrc + (ch + 1) * KC;
            const float* ms2 = msrc + (ch + 1) * KC;
            v[0] = *(const float4*)(zs2); v[1] = *(const float4*)(zs2 + 4);
            v[2] = *(const float4*)(ms2); v[3] = *(const float4*)(ms2 + 4);
        }

        // A fragments (2 x LDSM.x4), then B in two halves of 8 regs each
        uint32_t af[2][4];
        LDSM_X4(af[0][0], af[0][1], af[0][2], af[0][3], aA0 + boff);
        LDSM_X4(af[1][0], af[1][1], af[1][2], af[1][3], aA1 + boff);
        {
            uint32_t bf[4][2];
            LDSM_X4(bf[0][0], bf[0][1], bf[1][0], bf[1][1], bB[0] + boff);
            LDSM_X4(bf[2][0], bf[2][1], bf[3][0], bf[3][1], bB[1] + boff);
#pragma unroll
            for (int mt = 0; mt < 2; mt++)
#pragma unroll
                for (int nt = 0; nt < 4; nt++)
                    MMA16816(acc[mt][nt], af[mt], bf[nt][0], bf[nt][1]);
        }
        {
            uint32_t bf[4][2];
            LDSM_X4(bf[0][0], bf[0][1], bf[1][0], bf[1][1], bB[2] + boff);
            LDSM_X4(bf[2][0], bf[2][1], bf[3][0], bf[3][1], bB[3] + boff);
#pragma unroll
            for (int mt = 0; mt < 2; mt++)
#pragma unroll
                for (int nt = 0; nt < 4; nt++)
                    MMA16816(acc[mt][nt + 4], af[mt], bf[nt][0], bf[nt][1]);
        }

        if (ch < 63) {
            const uint32_t nboff = (uint32_t)((ch + 1) & 1) * BUFB;
            sqz = fmaf(v[0].x, v[0].x, sqz); sqz = fmaf(v[0].y, v[0].y, sqz);
            sqz = fmaf(v[0].z, v[0].z, sqz); sqz = fmaf(v[0].w, v[0].w, sqz);
            sqz = fmaf(v[1].x, v[1].x, sqz); sqz = fmaf(v[1].y, v[1].y, sqz);
            sqz = fmaf(v[1].z, v[1].z, sqz); sqz = fmaf(v[1].w, v[1].w, sqz);
            uint4 u;
            u.x = f2bf2(v[0].x, v[0].y); u.y = f2bf2(v[0].z, v[0].w);
            u.z = f2bf2(v[1].x, v[1].y); u.w = f2bf2(v[1].z, v[1].w);
            *(uint4*)(abp + nboff + stZ) = u;
            sqm = fmaf(v[2].x, v[2].x, sqm); sqm = fmaf(v[2].y, v[2].y, sqm);
            sqm = fmaf(v[2].z, v[2].z, sqm); sqm = fmaf(v[2].w, v[2].w, sqm);
            sqm = fmaf(v[3].x, v[3].x, sqm); sqm = fmaf(v[3].y, v[3].y, sqm);
            sqm = fmaf(v[3].z, v[3].z, sqm); sqm = fmaf(v[3].w, v[3].w, sqm);
            uint4 u2;
            u2.x = f2bf2(v[2].x, v[2].y); u2.y = f2bf2(v[2].z, v[2].w);
            u2.z = f2bf2(v[3].x, v[3].y); u2.w = f2bf2(v[3].z, v[3].w);
            *(uint4*)(abp + nboff + stM) = u2;
        }
    }

    // row norms: combine half-row partials (adjacent lanes)
    {
        float oz = __shfl_xor_sync(0xffffffffu, sqz, 1);
        float om = __shfl_xor_sync(0xffffffffu, sqm, 1);
        if (half == 0) {
            zn_s[lrow] = sqz + oz;
            mn_s[lrow] = sqm + om;
        }
    }
    __syncthreads();   // all MMA/LDSM done -> overwrite AB as xp

    // stage acc -> xp[128][129]
    {
        const int rA = lane >> 2;
#pragma unroll
        for (int mt = 0; mt < 2; mt++)
#pragma unroll
            for (int nt = 0; nt < 8; nt++)
#pragma unroll
                for (int r = 0; r < 4; r++) {
                    int row = wm * 32 + mt * 16 + rA + 8 * (r >> 1);
                    int col = wn * 64 + nt * 8 + 2 * (lane & 3) + (r & 1);
                    xp[row][col] = acc[mt][nt][r];
                }
    }
    __syncthreads();

    // stats + candidate emit: 2 threads per row, 64 cols each
    {
        const int row = t >> 1;
        const int q   = t & 1;
        const int c   = yc_s[row];
        const float znv = zn_s[row];
        float pmax = NEG_INF, nsum = 0.f;
#pragma unroll 8
        for (int i = 0; i < 64; i++) {
            int col = q * 64 + i;
            float d  = fmaf(-2.f, xp[row][col], znv + mn_s[col]);
            float x  = d + EPS_C;
            float dl = (1.f - EPS_C) * rcp_newton(x);
            float rr = 1.f + dl;
            float r2 = rr * rr;
            float s  = r2 * r2 * rr;
            if ((col >> 3) == c) pmax = fmaxf(pmax, s);
            else nsum += s;
        }
        pm_s[q * 128 + row] = pmax;
        ns_s[q * 128 + row] = nsum;

        if (q == 0) {
            int rank = atomicAdd(&scnt[c], 1);
            if (rank < SPT) {
                int slot = tileIdx * SPT + rank;
                g_cidx[c * SPC + slot] = r0 + row;
#pragma unroll
                for (int m = 0; m < 8; m++) {
                    int col = 8 * c + m;
                    float d = fmaf(-2.f, xp[row][col], znv + mn_s[col]);
                    g_cval[(size_t)((c << 3) + m) * SPC + slot] = d;
                }
            }
        }
    }
    __syncthreads();

    if (t < 128) {
        float P = fmaxf(pm_s[t], pm_s[128 + t]);
        float S = ns_s[t] + ns_s[128 + t];
        loss_s[t] = log1pf(S / P);
    }
    if (t < 16) g_bcnt[t * NTILES + tileIdx] = min(scnt[t], SPT);
    __syncthreads();
    for (int s = 64; s > 0; s >>= 1) {
        if (t < s) loss_s[t] += loss_s[t + s];
        __syncthreads();
    }
    if (t == 0) g_loss_partial[tileIdx] = loss_s[0];
}

// ---------------- selection: warp-local top-32 + single-warp merge ----------------
#define CAPC 2560
#define TKT  512
#define NCV  5

__device__ __forceinline__ bool better(float av, int ai, float bv, int bi) {
    return (av > bv) || (av == bv && ai < bi);
}

__global__ __launch_bounds__(TKT)
void k_sel(float* __restrict__ out, int writeLoss) {
    __shared__ float sv[CAPC];
    __shared__ int   si[CAPC];
    __shared__ int   pre[256];
    __shared__ int   wsum[8], wscan[8];
    __shared__ float wtv[16][K2];
    __shared__ int   wti[16][K2];
    __shared__ float lred[256];
    __shared__ int   ntot;

    const int t    = threadIdx.x;
    const int lane = t & 31;
    const int w    = t >> 5;
    const int j    = blockIdx.x;
    const int c    = j >> 3;
    const int m    = j & 7;

    int cnt = 0;
    if (t < 256) {
        cnt = g_bcnt[c * NTILES + t];
        int v = cnt;
#pragma unroll
        for (int o = 1; o < 32; o <<= 1) {
            int nvv = __shfl_up_sync(0xffffffffu, v, o);
            if (lane >= o) v += nvv;
        }
        if (lane == 31) wsum[w] = v;
        pre[t] = v - cnt;
    }
    __syncthreads();
    if (t < 8) {
        int s = wsum[t];
#pragma unroll
        for (int o = 1; o < 8; o <<= 1) {
            int nvv = __shfl_up_sync(0xffu, s, o);
            if ((t & 7) >= o) s += nvv;
        }
        wscan[t] = s;
    }
    __syncthreads();
    if (t < 256) {
        int excl = pre[t] + (w > 0 ? wscan[w - 1] : 0);
        pre[t] = excl;
        if (t == 255) ntot = min(excl + cnt, CAPC);
    }
    __syncthreads();

    if (t < 256) {
        const float* cvp = g_cval + (size_t)((c << 3) + m) * SPC + t * SPT;
        const int*   cip = g_cidx + (size_t)c * SPC + t * SPT;
        int off = pre[t];
        for (int i = 0; i < cnt; i++) {
            if (off + i < CAPC) { sv[off + i] = cvp[i]; si[off + i] = cip[i]; }
        }
    }
    __syncthreads();
    const int n = ntot;

    {
        float cv[NCV]; int ci[NCV];
#pragma unroll
        for (int u = 0; u < NCV; u++) {
            int p = t + u * TKT;
            if (p < n) { cv[u] = sv[p]; ci[u] = si[p]; }
            else       { cv[u] = NEG_INF; ci[u] = 0x7fffffff; }
        }
#pragma unroll 4
        for (int k = 0; k < K2; k++) {
            float bv = cv[0]; int bi = ci[0]; int bu = 0;
#pragma unroll
            for (int u = 1; u < NCV; u++)
                if (better(cv[u], ci[u], bv, bi)) { bv = cv[u]; bi = ci[u]; bu = u; }
            float rv = bv; int ri = bi; int rl = lane;
#pragma unroll
            for (int o = 16; o > 0; o >>= 1) {
                float ov = __shfl_xor_sync(0xffffffffu, rv, o);
                int   oi = __shfl_xor_sync(0xffffffffu, ri, o);
                int   ol = __shfl_xor_sync(0xffffffffu, rl, o);
                if (better(ov, oi, rv, ri)) { rv = ov; ri = oi; rl = ol; }
            }
            if (lane == 0) { wtv[w][k] = rv; wti[w][k] = ri; }
            {
                const bool win = (lane == rl);
#pragma unroll
                for (int u = 0; u < NCV; u++) {
                    bool kill = win && (u == bu);
                    cv[u] = kill ? NEG_INF : cv[u];
                    ci[u] = kill ? 0x7fffffff : ci[u];
                }
            }
        }
    }
    __syncthreads();

    if (w == 0) {
        int head = 0;
        float hv = (lane < 16) ? wtv[lane][0] : NEG_INF;
        int   hi = (lane < 16) ? wti[lane][0] : 0x7fffffff;
        for (int k = 0; k < K2; k++) {
            float rv = hv; int ri = hi; int rl = lane;
#pragma unroll
            for (int o = 16; o > 0; o >>= 1) {
                float ov = __shfl_xor_sync(0xffffffffu, rv, o);
                int   oi = __shfl_xor_sync(0xffffffffu, ri, o);
                int   ol = __shfl_xor_sync(0xffffffffu, rl, o);
                if (better(ov, oi, rv, ri)) { rv = ov; ri = oi; rl = ol; }
            }
            if (lane == 0) g_sel[j][k] = (rv == NEG_INF) ? 0 : ri;
            if (lane == rl) {
                head++;
                hv = (head < K2) ? wtv[lane][head] : NEG_INF;
                hi = (head < K2) ? wti[lane][head] : 0x7fffffff;
            }
        }
    }

    if (j == 0 && writeLoss) {
        __syncthreads();
        if (t < 256) lred[t] = g_loss_partial[t];
        __syncthreads();
        for (int s = 128; s > 0; s >>= 1) {
            if (t < s) lred[t] += lred[t + s];
            __syncthreads();
        }
        if (t == 0) out[0] = lred[0] * (1.f / (float)N_ROWS);
    }
}

// ---------------- update: bandwidth-bound gather-mean + EMA blend ----------------
__global__ __launch_bounds__(256)
void k_upd(const float* __restrict__ z, const float* __restrict__ M,
           float* __restrict__ out, int moff) {
    __shared__ int sel_s[K2];
    const int t = threadIdx.x;
    const int j = blockIdx.x >> 2;
    const int s = blockIdx.x & 3;
    const int col = s * 256 + t;

    if (t < K2) sel_s[t] = g_sel[j][t];
    __syncthreads();

    float a = 0.f;
#pragma unroll 8
    for (int k = 0; k < K2; k++)
        a += z[(size_t)sel_s[k] * HDIM + col];

    out[moff + (size_t)j * HDIM + col] =
        TAU_C * M[(size_t)j * HDIM + col] + (1.f - TAU_C) * (a * (1.f / (float)K2));
}

// ---------------- entry ----------------
extern "C" void kernel_launch(void* const* d_in, const int* in_sizes, int n_in,
                              void* d_out, int out_size) {
    const float* z = (const float*)d_in[0];
    const float* M = (const float*)d_in[1];
    const int*   y = (const int*)d_in[2];
    float* out = (float*)d_out;

    int moff, writeM, writeLoss;
    if (out_size >= N_MOTIF * HDIM + 1)  { moff = 1; writeM = 1; writeLoss = 1; }
    else if (out_size >= N_MOTIF * HDIM) { moff = 0; writeM = 1; writeLoss = 0; }
    else                                 { moff = 0; writeM = 0; writeLoss = 1; }

    cudaFuncSetAttribute(k_gemm, cudaFuncAttributeMaxDynamicSharedMemorySize, SMEMB);

    k_gemm<<<NTILES, 256, SMEMB>>>(z, M, y);
    k_sel<<<N_MOTIF, TKT>>>(out, writeLoss);
    if (writeM) k_upd<<<N_MOTIF * 4, 256>>>(z, M, out, moff);
}

// round 17
// speedup vs baseline: 1.8152x; 1.0686x over previous
#include <cuda_runtime.h>
#include <cuda_bf16.h>
#include <cstdint>

#define N_ROWS   32768
#define HDIM     1024
#define N_MOTIF  128
#define N_CLASS  16
#define K2       32
#define EPS_C    1e-4f
#define TAU_C    0.99f

#define NTILES   256
#define SPT      32
#define SPC      (NTILES * SPT)

// ---------------- device scratch ----------------
__device__ float g_cval[(size_t)N_CLASS * 8 * SPC];
__device__ int   g_cidx[(size_t)N_CLASS * SPC];
__device__ int   g_bcnt[N_CLASS * NTILES];
__device__ float g_loss_partial[NTILES];
__device__ int   g_sel[N_MOTIF][K2];
__device__ __align__(16) __nv_bfloat16 g_mbf[N_MOTIF * HDIM];  // M pre-converted to bf16
__device__ float g_mn[N_MOTIF];                                 // M row norms

#define NEG_INF __int_as_float(0xff800000)

__device__ __forceinline__ uint32_t smem_u32(const void* p) {
    uint32_t a;
    asm("{ .reg .u64 t; cvta.to.shared.u64 t, %1; cvt.u32.u64 %0, t; }" : "=r"(a) : "l"(p));
    return a;
}
__device__ __forceinline__ float rcp_newton(float x) {
    float y = __uint_as_float(0x7EF311C3u - __float_as_uint(x));
    y = y * fmaf(-x, y, 2.f);
    y = y * fmaf(-x, y, 2.f);
    y = y * fmaf(-x, y, 2.f);
    return y;
}
__device__ __forceinline__ uint32_t f2bf2(float lo, float hi) {
    __nv_bfloat162 h = __floats2bfloat162_rn(lo, hi);
    return *(uint32_t*)&h;
}
#define LDSM_X4(r0, r1, r2, r3, addr) \
    asm volatile("ldmatrix.sync.aligned.m8n8.x4.shared.b16 {%0,%1,%2,%3}, [%4];" \
        : "=r"(r0), "=r"(r1), "=r"(r2), "=r"(r3) : "r"(addr))

#define MMA16816(ACC, AF, B0, B1)                                               \
    asm volatile(                                                               \
        "mma.sync.aligned.m16n8k16.row.col.f32.bf16.bf16.f32 "                  \
        "{%0,%1,%2,%3},{%4,%5,%6,%7},{%8,%9},{%0,%1,%2,%3};"                    \
        : "+f"((ACC)[0]), "+f"((ACC)[1]), "+f"((ACC)[2]), "+f"((ACC)[3])        \
        : "r"((AF)[0]), "r"((AF)[1]), "r"((AF)[2]), "r"((AF)[3]),               \
          "r"(B0), "r"(B1))

#define CP_ASYNC16(dst, src) \
    asm volatile("cp.async.ca.shared.global [%0], [%1], 16;" :: "r"(dst), "l"(src) : "memory")
#define CP_COMMIT() asm volatile("cp.async.commit_group;" ::: "memory")
#define CP_WAIT1()  asm volatile("cp.async.wait_group 1;" ::: "memory")
#define CP_WAIT0()  asm volatile("cp.async.wait_group 0;" ::: "memory")

// ---------------- smem layout: KC=16, KP=24 (48B rows); z: 2 bufs, M: 4 bufs ----------------
#define KC      16
#define KP      24
#define RB      (KP * 2)         // 48B per row
#define ZBUF    (128 * RB)       // 6144 B
#define MBUF    (128 * RB)       // 6144 B
#define SM_ZB   0                // 2 x 6144 = 12288
#define SM_MB   12288            // 4 x 6144 = 24576 -> ends 36864 (union with xp 66048)
#define XPS     129
#define SM_P    66048
#define SM_YC   (SM_P)
#define SM_ZN   (SM_P + 512)
#define SM_MN   (SM_P + 1024)
#define SM_PM   (SM_P + 1536)    // [2][128]
#define SM_NS   (SM_P + 2560)    // [2][128]
#define SM_LOSS (SM_P + 3584)
#define SM_SCNT (SM_P + 4096)
#define SM_MISC (SM_P + 4160)
#define SMEMB   (SM_P + 4224)

// ---------------- prepass: M fp32 -> bf16 + row norms ----------------
__global__ __launch_bounds__(256)
void k_prep(const float* __restrict__ Mv) {
    __shared__ float red[8];
    const int j = blockIdx.x;
    const int t = threadIdx.x;
    const int lane = t & 31;
    const int w = t >> 5;

    float4 x = *(const float4*)(Mv + (size_t)j * HDIM + t * 4);
    float s = 0.f;
    s = fmaf(x.x, x.x, s); s = fmaf(x.y, x.y, s);
    s = fmaf(x.z, x.z, s); s = fmaf(x.w, x.w, s);
    uint2 u;
    u.x = f2bf2(x.x, x.y); u.y = f2bf2(x.z, x.w);
    *(uint2*)(g_mbf + (size_t)j * HDIM + t * 4) = u;

#pragma unroll
    for (int o = 16; o > 0; o >>= 1) s += __shfl_xor_sync(0xffffffffu, s, o);
    if (lane == 0) red[w] = s;
    __syncthreads();
    if (t == 0) {
        float tot = red[0];
        for (int q = 1; q < 8; q++) tot += red[q];
        g_mn[j] = tot;
    }
}

// ---------------- fused GEMM + distance + loss + candidate emit ----------------
// 256 threads (8 warps 4x2), warp tile 32x64, block tile 128x128, grid 256, 2 CTAs/SM.
// z: fp32 LDG (distance-2 prefetch) + convert + STS, 2 buffers.
// M: bf16 cp.async from g_mbf, 4-buffer ring, depth-2 pipeline.
__global__ __launch_bounds__(256, 2)
void k_gemm(const float* __restrict__ z, const int* __restrict__ yraw) {
    extern __shared__ char dsm[];
    float (*xp)[XPS]   = (float(*)[XPS])(dsm);
    int*   yc_s  = (int*)  (dsm + SM_YC);
    float* zn_s  = (float*)(dsm + SM_ZN);
    float* mn_s  = (float*)(dsm + SM_MN);
    float* pm_s  = (float*)(dsm + SM_PM);
    float* ns_s  = (float*)(dsm + SM_NS);
    float* loss_s= (float*)(dsm + SM_LOSS);
    int*   scnt  = (int*)  (dsm + SM_SCNT);
    int*   is64p = (int*)  (dsm + SM_MISC);
    char*  zbp   = dsm + SM_ZB;

    const int t    = threadIdx.x;
    const int lane = t & 31;
    const int w    = t >> 5;
    const int wm   = w >> 1;
    const int wn   = w & 1;

    const int lrow = t >> 1;
    const int half = t & 1;
    const uint32_t stZ  = (uint32_t)(lrow * RB + half * 16);   // z staging offset in a zbuf
    const uint32_t mDst = smem_u32(dsm + SM_MB) + lrow * RB + half * 16;

    const int tileIdx = blockIdx.x;
    const int r0 = tileIdx * 128;

    if (t == 0) {
        int f = 1;
        for (int i = 0; i < 32; i++)
            if (yraw[2 * i + 1] != 0) { f = 0; break; }
        *is64p = f;
    }
    if (t < 16)  scnt[t] = 0;
    if (t < 128) mn_s[t] = g_mn[t];

    // ldmatrix base addresses (buffer 0 of each region)
    uint32_t aA0, aA1, bB[4];
    {
        __nv_bfloat16 (*sZ)[KP] = (__nv_bfloat16(*)[KP])zbp;
        __nv_bfloat16 (*sM)[KP] = (__nv_bfloat16(*)[KP])(dsm + SM_MB);
        int arow = wm * 32 + (lane & 15);
        int acol = (lane < 16) ? 0 : 8;
        int g    = lane >> 3;
        int bk   = (g & 1) * 8;
        int bnb  = (g >= 2) ? 8 : 0;
        aA0 = smem_u32(&sZ[arow][acol]);
        aA1 = smem_u32(&sZ[arow + 16][acol]);
#pragma unroll
        for (int p = 0; p < 4; p++) {
            int n = wn * 64 + p * 16 + bnb + (lane & 7);
            bB[p] = smem_u32(&sM[n][bk]);
        }
    }
    __syncthreads();
    const int is64 = *is64p;
    if (t < 128) yc_s[t] = is64 ? yraw[2 * (r0 + t)] : yraw[r0 + t];

    const float*         zsrc = z + (size_t)(r0 + lrow) * HDIM + half * 8;
    const __nv_bfloat16* msrc = g_mbf + (size_t)lrow * HDIM + half * 8;

    float acc[2][8][4];
#pragma unroll
    for (int a = 0; a < 2; a++)
#pragma unroll
        for (int b = 0; b < 8; b++)
#pragma unroll
            for (int c = 0; c < 4; c++) acc[a][b][c] = 0.f;
    float sqz = 0.f;

    // prologue: M chunks 0,1 via cp.async; z chunk0 -> zb0; z chunk1 -> vB
    CP_ASYNC16(mDst + 0 * MBUF, msrc + 0 * KC);
    CP_COMMIT();
    CP_ASYNC16(mDst + 1 * MBUF, msrc + 1 * KC);
    CP_COMMIT();

    float4 vA0, vA1, vB0, vB1;
    {
        float4 p0 = *(const float4*)(zsrc);
        float4 p1 = *(const float4*)(zsrc + 4);
        sqz = fmaf(p0.x, p0.x, sqz); sqz = fmaf(p0.y, p0.y, sqz);
        sqz = fmaf(p0.z, p0.z, sqz); sqz = fmaf(p0.w, p0.w, sqz);
        sqz = fmaf(p1.x, p1.x, sqz); sqz = fmaf(p1.y, p1.y, sqz);
        sqz = fmaf(p1.z, p1.z, sqz); sqz = fmaf(p1.w, p1.w, sqz);
        uint4 u;
        u.x = f2bf2(p0.x, p0.y); u.y = f2bf2(p0.z, p0.w);
        u.z = f2bf2(p1.x, p1.y); u.w = f2bf2(p1.z, p1.w);
        *(uint4*)(zbp + stZ) = u;
        vB0 = *(const float4*)(zsrc + KC);
        vB1 = *(const float4*)(zsrc + KC + 4);
    }
    CP_WAIT1();        // M chunk0 arrived
    __syncthreads();

    // one pipeline step (macro over register set names)
#define GSTEP(CH, VS0, VS1, VL0, VL1)                                           \
    do {                                                                        \
        const int ch_ = (CH);                                                   \
        if (ch_ < 62) {                                                         \
            VL0 = *(const float4*)(zsrc + (ch_ + 2) * KC);                      \
            VL1 = *(const float4*)(zsrc + (ch_ + 2) * KC + 4);                  \
            CP_ASYNC16(mDst + ((ch_ + 2) & 3) * MBUF, msrc + (ch_ + 2) * KC);   \
            CP_COMMIT();                                                        \
        }                                                                       \
        {                                                                       \
            const uint32_t zo = (uint32_t)(ch_ & 1) * ZBUF;                     \
            const uint32_t mo = (uint32_t)(ch_ & 3) * MBUF;                     \
            uint32_t af[2][4];                                                  \
            LDSM_X4(af[0][0], af[0][1], af[0][2], af[0][3], aA0 + zo);          \
            LDSM_X4(af[1][0], af[1][1], af[1][2], af[1][3], aA1 + zo);          \
            {                                                                   \
                uint32_t bf[4][2];                                              \
                LDSM_X4(bf[0][0], bf[0][1], bf[1][0], bf[1][1], bB[0] + mo);    \
                LDSM_X4(bf[2][0], bf[2][1], bf[3][0], bf[3][1], bB[1] + mo);    \
                _Pragma("unroll")                                               \
                for (int mt = 0; mt < 2; mt++)                                  \
                    _Pragma("unroll")                                           \
                    for (int nt = 0; nt < 4; nt++)                              \
                        MMA16816(acc[mt][nt], af[mt], bf[nt][0], bf[nt][1]);    \
            }                                                                   \
            {                                                                   \
                uint32_t bf[4][2];                                              \
                LDSM_X4(bf[0][0], bf[0][1], bf[1][0], bf[1][1], bB[2] + mo);    \
                LDSM_X4(bf[2][0], bf[2][1], bf[3][0], bf[3][1], bB[3] + mo);    \
                _Pragma("unroll")                                               \
                for (int mt = 0; mt < 2; mt++)                                  \
                    _Pragma("unroll")                                           \
                    for (int nt = 0; nt < 4; nt++)                              \
                        MMA16816(acc[mt][nt + 4], af[mt], bf[nt][0], bf[nt][1]);\
            }                                                                   \
        }                                                                       \
        if (ch_ < 63) {                                                         \
            sqz = fmaf(VS0.x, VS0.x, sqz); sqz = fmaf(VS0.y, VS0.y, sqz);       \
            sqz = fmaf(VS0.z, VS0.z, sqz); sqz = fmaf(VS0.w, VS0.w, sqz);       \
            sqz = fmaf(VS1.x, VS1.x, sqz); sqz = fmaf(VS1.y, VS1.y, sqz);       \
            sqz = fmaf(VS1.z, VS1.z, sqz); sqz = fmaf(VS1.w, VS1.w, sqz);       \
            uint4 u;                                                            \
            u.x = f2bf2(VS0.x, VS0.y); u.y = f2bf2(VS0.z, VS0.w);               \
            u.z = f2bf2(VS1.x, VS1.y); u.w = f2bf2(VS1.z, VS1.w);               \
            *(uint4*)(zbp + (uint32_t)((ch_ + 1) & 1) * ZBUF + stZ) = u;        \
        }                                                                       \
        if (ch_ >= 62) { CP_WAIT0(); } else { CP_WAIT1(); }                     \
        __syncthreads();                                                        \
    } while (0)

    for (int cg = 0; cg < 32; cg++) {
        GSTEP(2 * cg,     vB0, vB1, vA0, vA1);
        GSTEP(2 * cg + 1, vA0, vA1, vB0, vB1);
    }
#undef GSTEP

    // z row norms: combine half-row partials (adjacent lanes)
    {
        float oz = __shfl_xor_sync(0xffffffffu, sqz, 1);
        if (half == 0) zn_s[lrow] = sqz + oz;
    }
    __syncthreads();   // all MMA/LDSM done -> overwrite buffers as xp

    // stage acc -> xp[128][129]
    {
        const int rA = lane >> 2;
#pragma unroll
        for (int mt = 0; mt < 2; mt++)
#pragma unroll
            for (int nt = 0; nt < 8; nt++)
#pragma unroll
                for (int r = 0; r < 4; r++) {
                    int row = wm * 32 + mt * 16 + rA + 8 * (r >> 1);
                    int col = wn * 64 + nt * 8 + 2 * (lane & 3) + (r & 1);
                    xp[row][col] = acc[mt][nt][r];
                }
    }
    __syncthreads();

    // stats + candidate emit: 2 threads per row, 64 cols each
    {
        const int row = t >> 1;
        const int q   = t & 1;
        const int c   = yc_s[row];
        const float znv = zn_s[row];
        float pmax = NEG_INF, nsum = 0.f;
#pragma unroll 8
        for (int i = 0; i < 64; i++) {
            int col = q * 64 + i;
            float d  = fmaf(-2.f, xp[row][col], znv + mn_s[col]);
            float x  = d + EPS_C;
            float dl = (1.f - EPS_C) * rcp_newton(x);
            float rr = 1.f + dl;
            float r2 = rr * rr;
            float s  = r2 * r2 * rr;
            if ((col >> 3) == c) pmax = fmaxf(pmax, s);
            else nsum += s;
        }
        pm_s[q * 128 + row] = pmax;
        ns_s[q * 128 + row] = nsum;

        if (q == 0) {
            int rank = atomicAdd(&scnt[c], 1);
            if (rank < SPT) {
                int slot = tileIdx * SPT + rank;
                g_cidx[c * SPC + slot] = r0 + row;
#pragma unroll
                for (int m = 0; m < 8; m++) {
                    int col = 8 * c + m;
                    float d = fmaf(-2.f, xp[row][col], znv + mn_s[col]);
                    g_cval[(size_t)((c << 3) + m) * SPC + slot] = d;
                }
            }
        }
    }
    __syncthreads();

    if (t < 128) {
        float P = fmaxf(pm_s[t], pm_s[128 + t]);
        float S = ns_s[t] + ns_s[128 + t];
        loss_s[t] = log1pf(S / P);
    }
    if (t < 16) g_bcnt[t * NTILES + tileIdx] = min(scnt[t], SPT);
    __syncthreads();
    for (int s = 64; s > 0; s >>= 1) {
        if (t < s) loss_s[t] += loss_s[t + s];
        __syncthreads();
    }
    if (t == 0) g_loss_partial[tileIdx] = loss_s[0];
}

// ---------------- selection: warp-local top-32 + single-warp merge ----------------
#define CAPC 2560
#define TKT  512
#define NCV  5

__device__ __forceinline__ bool better(float av, int ai, float bv, int bi) {
    return (av > bv) || (av == bv && ai < bi);
}

__global__ __launch_bounds__(TKT)
void k_sel(float* __restrict__ out, int writeLoss) {
    __shared__ float sv[CAPC];
    __shared__ int   si[CAPC];
    __shared__ int   pre[256];
    __shared__ int   wsum[8], wscan[8];
    __shared__ float wtv[16][K2];
    __shared__ int   wti[16][K2];
    __shared__ float lred[256];
    __shared__ int   ntot;

    const int t    = threadIdx.x;
    const int lane = t & 31;
    const int w    = t >> 5;
    const int j    = blockIdx.x;
    const int c    = j >> 3;
    const int m    = j & 7;

    int cnt = 0;
    if (t < 256) {
        cnt = g_bcnt[c * NTILES + t];
        int v = cnt;
#pragma unroll
        for (int o = 1; o < 32; o <<= 1) {
            int nvv = __shfl_up_sync(0xffffffffu, v, o);
            if (lane >= o) v += nvv;
        }
        if (lane == 31) wsum[w] = v;
        pre[t] = v - cnt;
    }
    __syncthreads();
    if (t < 8) {
        int s = wsum[t];
#pragma unroll
        for (int o = 1; o < 8; o <<= 1) {
            int nvv = __shfl_up_sync(0xffu, s, o);
            if ((t & 7) >= o) s += nvv;
        }
        wscan[t] = s;
    }
    __syncthreads();
    if (t < 256) {
        int excl = pre[t] + (w > 0 ? wscan[w - 1] : 0);
        pre[t] = excl;
        if (t == 255) ntot = min(excl + cnt, CAPC);
    }
    __syncthreads();

    if (t < 256) {
        const float* cvp = g_cval + (size_t)((c << 3) + m) * SPC + t * SPT;
        const int*   cip = g_cidx + (size_t)c * SPC + t * SPT;
        int off = pre[t];
        for (int i = 0; i < cnt; i++) {
            if (off + i < CAPC) { sv[off + i] = cvp[i]; si[off + i] = cip[i]; }
        }
    }
    __syncthreads();
    const int n = ntot;

    {
        float cv[NCV]; int ci[NCV];
#pragma unroll
        for (int u = 0; u < NCV; u++) {
            int p = t + u * TKT;
            if (p < n) { cv[u] = sv[p]; ci[u] = si[p]; }
            else       { cv[u] = NEG_INF; ci[u] = 0x7fffffff; }
        }
#pragma unroll 4
        for (int k = 0; k < K2; k++) {
            float bv = cv[0]; int bi = ci[0]; int bu = 0;
#pragma unroll
            for (int u = 1; u < NCV; u++)
                if (better(cv[u], ci[u], bv, bi)) { bv = cv[u]; bi = ci[u]; bu = u; }
            float rv = bv; int ri = bi; int rl = lane;
#pragma unroll
            for (int o = 16; o > 0; o >>= 1) {
                float ov = __shfl_xor_sync(0xffffffffu, rv, o);
                int   oi = __shfl_xor_sync(0xffffffffu, ri, o);
                int   ol = __shfl_xor_sync(0xffffffffu, rl, o);
                if (better(ov, oi, rv, ri)) { rv = ov; ri = oi; rl = ol; }
            }
            if (lane == 0) { wtv[w][k] = rv; wti[w][k] = ri; }
            {
                const bool win = (lane == rl);
#pragma unroll
                for (int u = 0; u < NCV; u++) {
                    bool kill = win && (u == bu);
                    cv[u] = kill ? NEG_INF : cv[u];
                    ci[u] = kill ? 0x7fffffff : ci[u];
                }
            }
        }
    }
    __syncthreads();

    if (w == 0) {
        int head = 0;
        float hv = (lane < 16) ? wtv[lane][0] : NEG_INF;
        int   hi = (lane < 16) ? wti[lane][0] : 0x7fffffff;
        for (int k = 0; k < K2; k++) {
            float rv = hv; int ri = hi; int rl = lane;
#pragma unroll
            for (int o = 16; o > 0; o >>= 1) {
                float ov = __shfl_xor_sync(0xffffffffu, rv, o);
                int   oi = __shfl_xor_sync(0xffffffffu, ri, o);
                int   ol = __shfl_xor_sync(0xffffffffu, rl, o);
                if (better(ov, oi, rv, ri)) { rv = ov; ri = oi; rl = ol; }
            }
            if (lane == 0) g_sel[j][k] = (rv == NEG_INF) ? 0 : ri;
            if (lane == rl) {
                head++;
                hv = (head < K2) ? wtv[lane][head] : NEG_INF;
                hi = (head < K2) ? wti[lane][head] : 0x7fffffff;
            }
        }
    }

    if (j == 0 && writeLoss) {
        __syncthreads();
        if (t < 256) lred[t] = g_loss_partial[t];
        __syncthreads();
        for (int s = 128; s > 0; s >>= 1) {
            if (t < s) lred[t] += lred[t + s];
            __syncthreads();
        }
        if (t == 0) out[0] = lred[0] * (1.f / (float)N_ROWS);
    }
}

// ---------------- update: bandwidth-bound gather-mean + EMA blend ----------------
__global__ __launch_bounds__(256)
void k_upd(const float* __restrict__ z, const float* __restrict__ M,
           float* __restrict__ out, int moff) {
    __shared__ int sel_s[K2];
    const int t = threadIdx.x;
    const int j = blockIdx.x >> 2;
    const int s = blockIdx.x & 3;
    const int col = s * 256 + t;

    if (t < K2) sel_s[t] = g_sel[j][t];
    __syncthreads();

    float a = 0.f;
#pragma unroll 8
    for (int k = 0; k < K2; k++)
        a += z[(size_t)sel_s[k] * HDIM + col];

    out[moff + (size_t)j * HDIM + col] =
        TAU_C * M[(size_t)j * HDIM + col] + (1.f - TAU_C) * (a * (1.f / (float)K2));
}

// ---------------- entry ----------------
extern "C" void kernel_launch(void* const* d_in, const int* in_sizes, int n_in,
                              void* d_out, int out_size) {
    const float* z = (const float*)d_in[0];
    const float* M = (const float*)d_in[1];
    const int*   y = (const int*)d_in[2];
    float* out = (float*)d_out;

    int moff, writeM, writeLoss;
    if (out_size >= N_MOTIF * HDIM + 1)  { moff = 1; writeM = 1; writeLoss = 1; }
    else if (out_size >= N_MOTIF * HDIM) { moff = 0; writeM = 1; writeLoss = 0; }
    else                                 { moff = 0; writeM = 0; writeLoss = 1; }

    cudaFuncSetAttribute(k_gemm, cudaFuncAttributeMaxDynamicSharedMemorySize, SMEMB);

    k_prep<<<N_MOTIF, 256>>>(M);
    k_gemm<<<NTILES, 256, SMEMB>>>(z, y);
    k_sel<<<N_MOTIF, TKT>>>(out, writeLoss);
    if (writeM) k_upd<<<N_MOTIF * 4, 256>>>(z, M, out, moff);
}